// round 1
// baseline (speedup 1.0000x reference)
#include <cuda_runtime.h>
#include <math.h>

// ContinuousRelativePositionalBias, fused 3-layer MLP over 4*512*512 points.
// out[(b*4+o), i, j] = (relu(relu(bias(b,i,j) @ W1 + b1) @ W2 + b2) @ W3 + b3)[o]
// bias(b,i,j)[c] = sign(p)*log1p(|p|), p = grid_q[i,c] - grid_kv[b,j,c]
//
// Round 0: fused fp32 FFMA kernel. One CTA = 128 points (one j-strip) for a
// fixed (b,i). W2 cached in smem (64KB), H1 tile in smem (stride-129 padded),
// register-blocked 8x8 SGEMM for layer 2.

#define ID 512
#define JD 512
#define BD 4
#define DD 128
#define OD 4
#define TILE 128        // points (j) per block
#define NTHREADS 256
#define H1S 129         // padded H1 row stride (floats) - kills p-stride bank conflicts

// dynamic smem layout (in floats)
#define OFF_W2   0                          // 128*128        = 16384
#define OFF_H1   16384                      // 128*129        = 16512
#define OFF_W1   (OFF_H1 + TILE*H1S)        // 3*128
#define OFF_B1   (OFF_W1 + 3*DD)            // 128
#define OFF_B2   (OFF_B1 + DD)              // 128
#define OFF_W3   (OFF_B2 + DD)              // 128*4 (16B aligned: OFF_W3 %4==0)
#define OFF_B3   (OFF_W3 + DD*OD)           // 4 (+pad)
#define OFF_BIAS (OFF_B3 + 8)               // 3*128, layout [c][p]
#define SMEM_FLOATS (OFF_BIAS + 3*TILE)
#define SMEM_BYTES  (SMEM_FLOATS * 4)

__global__ __launch_bounds__(NTHREADS, 1)
void crpb_kernel(const float* __restrict__ grid_q,
                 const float* __restrict__ grid_kv,
                 const float* __restrict__ W1, const float* __restrict__ b1,
                 const float* __restrict__ W2, const float* __restrict__ b2,
                 const float* __restrict__ W3, const float* __restrict__ b3,
                 float* __restrict__ out)
{
    extern __shared__ float smem[];
    float* sW2   = smem + OFF_W2;
    float* sH1   = smem + OFF_H1;
    float* sW1   = smem + OFF_W1;
    float* sb1   = smem + OFF_B1;
    float* sb2   = smem + OFF_B2;
    float* sW3   = smem + OFF_W3;
    float* sb3   = smem + OFF_B3;
    float* sBias = smem + OFF_BIAS;   // [c][p]

    const int tid = threadIdx.x;
    const int bx  = blockIdx.x;
    const int jt  = bx & 3;            // 4 j-tiles per (b,i)
    const int i   = (bx >> 2) & (ID - 1);
    const int b   = bx >> 11;          // 8192 blocks / 2048 per b
    const int j0  = jt * TILE;

    // ---- load W2 (vectorized), small params ----
    {
        const float4* g = reinterpret_cast<const float4*>(W2);
        float4*       s = reinterpret_cast<float4*>(sW2);
        #pragma unroll
        for (int it = 0; it < (DD*DD/4)/NTHREADS; ++it)
            s[tid + it*NTHREADS] = g[tid + it*NTHREADS];
    }
    if (tid < DD) {
        sb1[tid] = b1[tid];
        sb2[tid] = b2[tid];
        sW1[tid]        = W1[tid];
        sW1[tid + 128]  = W1[tid + 128];
        sW1[tid + 256]  = W1[tid + 256];
        reinterpret_cast<float4*>(sW3)[tid] = reinterpret_cast<const float4*>(W3)[tid];
    }
    if (tid < OD) sb3[tid] = b3[tid];

    // ---- bias per point ----
    if (tid < TILE) {
        const int j = j0 + tid;
        #pragma unroll
        for (int c = 0; c < 3; ++c) {
            float pos = grid_q[i*3 + c] - grid_kv[(b*JD + j)*3 + c];
            sBias[c*TILE + tid] = copysignf(log1pf(fabsf(pos)), pos);
        }
    }
    __syncthreads();

    // ---- phase 1: H1[p][d] = relu(bias . W1[:,d] + b1[d]) ----
    {
        const int p  = tid & (TILE - 1);
        const int d0 = tid >> 7;   // 0 or 1
        const float bs0 = sBias[0*TILE + p];
        const float bs1 = sBias[1*TILE + p];
        const float bs2 = sBias[2*TILE + p];
        #pragma unroll 8
        for (int d = d0; d < DD; d += 2) {
            float h = fmaf(bs0, sW1[d],
                      fmaf(bs1, sW1[128 + d],
                      fmaf(bs2, sW1[256 + d], sb1[d])));
            sH1[p*H1S + d] = fmaxf(h, 0.0f);
        }
    }
    __syncthreads();

    // ---- phase 2: H2 = H1[128,128] @ W2[128,128] + b2 (register-blocked) ----
    const int tp = tid >> 4;   // 0..15 : point group (8 rows)
    const int te = tid & 15;   // 0..15 : col group (8 cols)
    float acc[8][8];
    #pragma unroll
    for (int c = 0; c < 8; ++c) {
        const float bb = sb2[te*8 + c];
        #pragma unroll
        for (int r = 0; r < 8; ++r) acc[r][c] = bb;
    }
    const float* h1base = sH1 + tp*8*H1S;
    const float* w2base = sW2 + te*8;
    #pragma unroll 2
    for (int k = 0; k < DD; ++k) {
        float a[8];
        #pragma unroll
        for (int r = 0; r < 8; ++r) a[r] = h1base[r*H1S + k];
        float4 w0 = *reinterpret_cast<const float4*>(w2base + k*DD);
        float4 w1 = *reinterpret_cast<const float4*>(w2base + k*DD + 4);
        float w[8] = {w0.x, w0.y, w0.z, w0.w, w1.x, w1.y, w1.z, w1.w};
        #pragma unroll
        for (int r = 0; r < 8; ++r)
            #pragma unroll
            for (int c = 0; c < 8; ++c)
                acc[r][c] = fmaf(a[r], w[c], acc[r][c]);
    }
    __syncthreads();   // everyone done reading H1

    // ---- phase 3: relu(H2) back into sH1 ----
    #pragma unroll
    for (int r = 0; r < 8; ++r) {
        const int p = tp*8 + r;
        #pragma unroll
        for (int c = 0; c < 8; ++c)
            sH1[p*H1S + te*8 + c] = fmaxf(acc[r][c], 0.0f);
    }
    __syncthreads();

    // ---- phase 4: layer 3 (128 -> 4) + coalesced store ----
    {
        const int p  = tid & (TILE - 1);
        const int ob = tid >> 7;    // 0/1 -> handles o = ob and o = 2+ob
        const float* h2 = sH1 + p*H1S;
        float v0 = sb3[ob];
        float v1 = sb3[2 + ob];
        #pragma unroll 8
        for (int e = 0; e < DD; ++e) {
            const float h = h2[e];
            v0 = fmaf(h, sW3[e*4 + ob],     v0);
            v1 = fmaf(h, sW3[e*4 + 2 + ob], v1);
        }
        const int o0 = ob;
        const int o1 = 2 + ob;
        out[((b*4 + o0)*ID + i)*JD + j0 + p] = v0;
        out[((b*4 + o1)*ID + i)*JD + j0 + p] = v1;
    }
}

extern "C" void kernel_launch(void* const* d_in, const int* in_sizes, int n_in,
                              void* d_out, int out_size)
{
    const float* grid_q  = (const float*)d_in[0];
    const float* grid_kv = (const float*)d_in[1];
    const float* W1      = (const float*)d_in[2];
    const float* b1      = (const float*)d_in[3];
    const float* W2      = (const float*)d_in[4];
    const float* b2      = (const float*)d_in[5];
    const float* W3      = (const float*)d_in[6];
    const float* b3      = (const float*)d_in[7];
    float* out = (float*)d_out;

    cudaFuncSetAttribute(crpb_kernel,
                         cudaFuncAttributeMaxDynamicSharedMemorySize, SMEM_BYTES);

    const int nblocks = BD * ID * (JD / TILE);   // 8192
    crpb_kernel<<<nblocks, NTHREADS, SMEM_BYTES>>>(
        grid_q, grid_kv, W1, b1, W2, b2, W3, b3, out);
}

// round 3
// speedup vs baseline: 2.6547x; 2.6547x over previous
#include <cuda_runtime.h>
#include <cuda_bf16.h>
#include <math.h>
#include <stdint.h>

// ContinuousRelativePositionalBias — Round 3: legacy tensor-core path
// (mma.sync m16n8k16 bf16 + ldmatrix; tcgen05 is unavailable because the
// harness's ptxas target is plain sm_103, not sm_103a).
//
//   bias(b,i,j)[3] -> H1 = relu(bias@W1+b1)      (registers -> smem bf16 hi/lo)
//   H2 = H1 @ W2 + b2                            (HMMA, 3 passes: Ah*Bh+Al*Bh+Ah*Bl)
//   out = relu(H2) @ W3 + b3                     (register epilogue + quad reduce)
//
// W2 pre-converted to bf16 hi/lo and pre-XOR-swizzled by a prep kernel.

#define ID 512
#define JD 512
#define BD 4
#define DD 128
#define TILE 128
#define NTHREADS 256

// XOR swizzle for 256B-row bf16 tiles: 16B chunk index ^= (row & 7)
#define SWZ(row, chunk) ((unsigned)(row) * 256u + ((((unsigned)(chunk)) ^ ((unsigned)(row) & 7u)) << 4))

// smem byte offsets
#define OFF_W2HI 0
#define OFF_W2LO 32768
#define OFF_H1HI 65536
#define OFF_H1LO 98304
#define OFF_RED  131072            // 2*128 float4 = 4096
#define OFF_W1   135168            // 384 floats
#define OFF_B1   136704            // 128 floats
#define OFF_B2   137216            // 128 floats
#define OFF_W3   137728            // 512 floats [e][o]
#define OFF_B3   139776            // 4 floats
#define SMEM_BYTES 139840

__device__ __align__(16) uint8_t g_w2hi[32768];
__device__ __align__(16) uint8_t g_w2lo[32768];

// ---------------- prep: W2 -> bf16 hi/lo, swizzled row-major [k][n] ----------------
__global__ void prep_w2(const float* __restrict__ W2) {
    int idx = blockIdx.x * blockDim.x + threadIdx.x;   // 16384
    if (idx >= DD * DD) return;
    int k = idx >> 7, n = idx & 127;
    float v = W2[idx];
    __nv_bfloat16 hb = __float2bfloat16_rn(v);
    float hf = __bfloat162float(hb);
    __nv_bfloat16 lb = __float2bfloat16_rn(v - hf);
    unsigned byte = SWZ(k, n >> 3) + (unsigned)(n & 7) * 2u;
    *(uint16_t*)(g_w2hi + byte) = __bfloat16_as_ushort(hb);
    *(uint16_t*)(g_w2lo + byte) = __bfloat16_as_ushort(lb);
}

// ---------------- PTX helpers ----------------
__device__ __forceinline__ uint32_t smem_u32(const void* p) {
    uint32_t a;
    asm("{ .reg .u64 t; cvta.to.shared.u64 t, %1; cvt.u32.u64 %0, t; }" : "=r"(a) : "l"(p));
    return a;
}
__device__ __forceinline__ void ldsm_x4(uint32_t& r0, uint32_t& r1, uint32_t& r2, uint32_t& r3,
                                        uint32_t addr) {
    asm volatile("ldmatrix.sync.aligned.m8n8.x4.shared.b16 {%0,%1,%2,%3}, [%4];"
                 : "=r"(r0), "=r"(r1), "=r"(r2), "=r"(r3) : "r"(addr));
}
__device__ __forceinline__ void ldsm_x2t(uint32_t& r0, uint32_t& r1, uint32_t addr) {
    asm volatile("ldmatrix.sync.aligned.m8n8.x2.trans.shared.b16 {%0,%1}, [%2];"
                 : "=r"(r0), "=r"(r1) : "r"(addr));
}
__device__ __forceinline__ void mma_bf16(float* c, const uint32_t* a, uint32_t b0, uint32_t b1) {
    asm volatile("mma.sync.aligned.m16n8k16.row.col.f32.bf16.bf16.f32 "
                 "{%0,%1,%2,%3}, {%4,%5,%6,%7}, {%8,%9}, {%0,%1,%2,%3};"
                 : "+f"(c[0]), "+f"(c[1]), "+f"(c[2]), "+f"(c[3])
                 : "r"(a[0]), "r"(a[1]), "r"(a[2]), "r"(a[3]), "r"(b0), "r"(b1));
}
#define CP_ASYNC16(dst, src) \
    asm volatile("cp.async.cg.shared.global [%0], [%1], 16;" :: "r"(dst), "l"(src) : "memory")
#define CP_ASYNC_COMMIT() asm volatile("cp.async.commit_group;" ::: "memory")
#define CP_ASYNC_WAIT0()  asm volatile("cp.async.wait_group 0;" ::: "memory")

// ---------------- main kernel ----------------
__global__ __launch_bounds__(NTHREADS, 1)
void crpb_hmma_kernel(const float* __restrict__ grid_q,
                      const float* __restrict__ grid_kv,
                      const float* __restrict__ W1, const float* __restrict__ b1,
                      const float* __restrict__ b2,
                      const float* __restrict__ W3, const float* __restrict__ b3,
                      float* __restrict__ out)
{
    extern __shared__ __align__(1024) char smem[];
    float* sW1 = (float*)(smem + OFF_W1);
    float* sb1 = (float*)(smem + OFF_B1);
    float* sb2 = (float*)(smem + OFF_B2);
    float* sW3 = (float*)(smem + OFF_W3);
    float* sb3 = (float*)(smem + OFF_B3);
    float4* red4 = (float4*)(smem + OFF_RED);

    const int tid  = threadIdx.x;
    const int lane = tid & 31;
    const int wid  = tid >> 5;
    const int bx   = blockIdx.x;
    const int jt   = bx & 3;
    const int i    = (bx >> 2) & (ID - 1);
    const int b    = bx >> 11;
    const int j0   = jt * TILE;

    // ---- params to smem ----
    for (int v = tid; v < 3 * DD; v += NTHREADS) sW1[v] = W1[v];
    for (int v = tid; v < DD; v += NTHREADS)     { sb1[v] = b1[v]; sb2[v] = b2[v]; }
    for (int v = tid; v < DD * 4; v += NTHREADS) sW3[v] = W3[v];
    if (tid < 4) sb3[tid] = b3[tid];

    // ---- kick off W2 hi/lo copy (cp.async, overlapped with H1 math) ----
    {
        uint32_t dhi = smem_u32(smem + OFF_W2HI) + tid * 16;
        uint32_t dlo = smem_u32(smem + OFF_W2LO) + tid * 16;
        const char* shi = (const char*)g_w2hi + tid * 16;
        const char* slo = (const char*)g_w2lo + tid * 16;
        #pragma unroll
        for (int it = 0; it < 8; ++it) {
            CP_ASYNC16(dhi + it * 4096, shi + it * 4096);
            CP_ASYNC16(dlo + it * 4096, slo + it * 4096);
        }
        CP_ASYNC_COMMIT();
    }
    __syncthreads();   // params ready

    // ---- H1 = relu(bias @ W1 + b1) -> smem bf16 hi/lo (swizzled) ----
    {
        const int p     = tid >> 1;
        const int dhalf = tid & 1;
        const int j     = j0 + p;
        float q0 = __ldg(grid_q + i * 3 + 0), q1 = __ldg(grid_q + i * 3 + 1), q2 = __ldg(grid_q + i * 3 + 2);
        float k0 = grid_kv[(b * JD + j) * 3 + 0];
        float k1 = grid_kv[(b * JD + j) * 3 + 1];
        float k2 = grid_kv[(b * JD + j) * 3 + 2];
        float p0 = q0 - k0, p1 = q1 - k1, p2 = q2 - k2;
        float bs0 = copysignf(log1pf(fabsf(p0)), p0);
        float bs1 = copysignf(log1pf(fabsf(p1)), p1);
        float bs2 = copysignf(log1pf(fabsf(p2)), p2);

        char* hbase = smem + OFF_H1HI;
        char* lbase = smem + OFF_H1LO;
        #pragma unroll
        for (int dd = 0; dd < 8; ++dd) {
            const int d0 = dhalf * 64 + dd * 8;
            uint32_t hi[4], lo[4];
            #pragma unroll
            for (int q = 0; q < 4; ++q) {
                int d = d0 + 2 * q;
                float h0 = fmaxf(fmaf(bs0, sW1[d],     fmaf(bs1, sW1[DD + d],     fmaf(bs2, sW1[2*DD + d],     sb1[d]))),     0.0f);
                float h1 = fmaxf(fmaf(bs0, sW1[d + 1], fmaf(bs1, sW1[DD + d + 1], fmaf(bs2, sW1[2*DD + d + 1], sb1[d + 1]))), 0.0f);
                __nv_bfloat162 hv = __floats2bfloat162_rn(h0, h1);
                float2 hf = __bfloat1622float2(hv);
                __nv_bfloat162 lv = __floats2bfloat162_rn(h0 - hf.x, h1 - hf.y);
                hi[q] = *(uint32_t*)&hv;
                lo[q] = *(uint32_t*)&lv;
            }
            unsigned off = SWZ(p, d0 >> 3);
            *(uint4*)(hbase + off) = make_uint4(hi[0], hi[1], hi[2], hi[3]);
            *(uint4*)(lbase + off) = make_uint4(lo[0], lo[1], lo[2], lo[3]);
        }
    }
    CP_ASYNC_WAIT0();
    __syncthreads();   // H1 + W2 tiles ready

    // ---- layer 2: HMMA, warp tile 32(M) x 64(N), 3 precision passes ----
    const int wm = wid & 3;           // M tile: rows wm*32 .. +31
    const int wn = wid >> 2;          // N tile: cols wn*64 .. +63
    const int g  = lane >> 2;
    const int t4 = lane & 3;

    float acc[2][8][4];
    #pragma unroll
    for (int mt = 0; mt < 2; ++mt)
        #pragma unroll
        for (int nt = 0; nt < 8; ++nt)
            #pragma unroll
            for (int c = 0; c < 4; ++c) acc[mt][nt][c] = 0.0f;

    const uint32_t h1hi_b = smem_u32(smem + OFF_H1HI);
    const uint32_t h1lo_b = smem_u32(smem + OFF_H1LO);
    const uint32_t w2hi_b = smem_u32(smem + OFF_W2HI);
    const uint32_t w2lo_b = smem_u32(smem + OFF_W2LO);

    // per-lane invariants
    const int arow   = wm * 32 + (lane & 15);   // A rows for mt=0 (mt=1 adds 16)
    const int ahi4   = lane >> 4;               // chunk offset from lane group
    const int brow_l = lane & 15;               // B row within k-chunk

    #pragma unroll
    for (int kc = 0; kc < 8; ++kc) {
        // A fragments (hi & lo) for both m-tiles
        uint32_t Ah[2][4], Al[2][4];
        #pragma unroll
        for (int mt = 0; mt < 2; ++mt) {
            int r = arow + mt * 16;
            unsigned off = SWZ(r, kc * 2 + ahi4);
            ldsm_x4(Ah[mt][0], Ah[mt][1], Ah[mt][2], Ah[mt][3], h1hi_b + off);
            ldsm_x4(Al[mt][0], Al[mt][1], Al[mt][2], Al[mt][3], h1lo_b + off);
        }
        int rb = kc * 16 + brow_l;
        unsigned boff_row = (unsigned)rb * 256u;
        unsigned bxor = (unsigned)(rb & 7) << 4;
        #pragma unroll
        for (int nt = 0; nt < 8; ++nt) {
            unsigned chunk = (unsigned)(wn * 8 + nt);
            unsigned boff = boff_row + (((chunk << 4) ^ bxor));
            uint32_t bh0, bh1, bl0, bl1;
            ldsm_x2t(bh0, bh1, w2hi_b + boff);
            ldsm_x2t(bl0, bl1, w2lo_b + boff);
            #pragma unroll
            for (int mt = 0; mt < 2; ++mt) {
                mma_bf16(acc[mt][nt], Ah[mt], bh0, bh1);
                mma_bf16(acc[mt][nt], Al[mt], bh0, bh1);
                mma_bf16(acc[mt][nt], Ah[mt], bl0, bl1);
            }
        }
    }

    // ---- epilogue: relu(H2 + b2) @ W3, in registers ----
    float ov[2][2][4];   // [mt][row-half][o]
    #pragma unroll
    for (int mt = 0; mt < 2; ++mt)
        #pragma unroll
        for (int h = 0; h < 2; ++h)
            #pragma unroll
            for (int o = 0; o < 4; ++o) ov[mt][h][o] = 0.0f;

    #pragma unroll
    for (int nt = 0; nt < 8; ++nt) {
        const int e0 = wn * 64 + nt * 8 + 2 * t4;
        float2 b2v = *(const float2*)(sb2 + e0);
        float4 w30 = *(const float4*)(sW3 + e0 * 4);
        float4 w31 = *(const float4*)(sW3 + (e0 + 1) * 4);
        #pragma unroll
        for (int mt = 0; mt < 2; ++mt) {
            float h00 = fmaxf(acc[mt][nt][0] + b2v.x, 0.0f);
            float h01 = fmaxf(acc[mt][nt][1] + b2v.y, 0.0f);
            float h10 = fmaxf(acc[mt][nt][2] + b2v.x, 0.0f);
            float h11 = fmaxf(acc[mt][nt][3] + b2v.y, 0.0f);
            ov[mt][0][0] = fmaf(h00, w30.x, fmaf(h01, w31.x, ov[mt][0][0]));
            ov[mt][0][1] = fmaf(h00, w30.y, fmaf(h01, w31.y, ov[mt][0][1]));
            ov[mt][0][2] = fmaf(h00, w30.z, fmaf(h01, w31.z, ov[mt][0][2]));
            ov[mt][0][3] = fmaf(h00, w30.w, fmaf(h01, w31.w, ov[mt][0][3]));
            ov[mt][1][0] = fmaf(h10, w30.x, fmaf(h11, w31.x, ov[mt][1][0]));
            ov[mt][1][1] = fmaf(h10, w30.y, fmaf(h11, w31.y, ov[mt][1][1]));
            ov[mt][1][2] = fmaf(h10, w30.z, fmaf(h11, w31.z, ov[mt][1][2]));
            ov[mt][1][3] = fmaf(h10, w30.w, fmaf(h11, w31.w, ov[mt][1][3]));
        }
    }
    // quad reduce (sum over t4 lanes)
    #pragma unroll
    for (int mt = 0; mt < 2; ++mt)
        #pragma unroll
        for (int h = 0; h < 2; ++h)
            #pragma unroll
            for (int o = 0; o < 4; ++o) {
                float v = ov[mt][h][o];
                v += __shfl_xor_sync(0xFFFFFFFF, v, 1);
                v += __shfl_xor_sync(0xFFFFFFFF, v, 2);
                ov[mt][h][o] = v;
            }
    if (t4 == 0) {
        #pragma unroll
        for (int mt = 0; mt < 2; ++mt)
            #pragma unroll
            for (int h = 0; h < 2; ++h) {
                int p = wm * 32 + mt * 16 + h * 8 + g;
                red4[wn * 128 + p] = make_float4(ov[mt][h][0], ov[mt][h][1], ov[mt][h][2], ov[mt][h][3]);
            }
    }
    __syncthreads();

    if (tid < TILE) {
        const int p = tid;
        float4 r0 = red4[p];
        float4 r1 = red4[128 + p];
        const long base = ((long)(b * 4) * ID + i) * JD + j0 + p;
        const long os   = (long)ID * JD;
        out[base]          = r0.x + r1.x + sb3[0];
        out[base + os]     = r0.y + r1.y + sb3[1];
        out[base + 2 * os] = r0.z + r1.z + sb3[2];
        out[base + 3 * os] = r0.w + r1.w + sb3[3];
    }
}

extern "C" void kernel_launch(void* const* d_in, const int* in_sizes, int n_in,
                              void* d_out, int out_size)
{
    const float* grid_q  = (const float*)d_in[0];
    const float* grid_kv = (const float*)d_in[1];
    const float* W1      = (const float*)d_in[2];
    const float* b1      = (const float*)d_in[3];
    const float* W2      = (const float*)d_in[4];
    const float* b2      = (const float*)d_in[5];
    const float* W3      = (const float*)d_in[6];
    const float* b3      = (const float*)d_in[7];
    float* out = (float*)d_out;

    prep_w2<<<DD * DD / 256, 256>>>(W2);

    cudaFuncSetAttribute(crpb_hmma_kernel,
                         cudaFuncAttributeMaxDynamicSharedMemorySize, SMEM_BYTES);
    const int nblocks = BD * ID * (JD / TILE);   // 8192
    crpb_hmma_kernel<<<nblocks, NTHREADS, SMEM_BYTES>>>(
        grid_q, grid_kv, W1, b1, b2, W3, b3, out);
}